// round 11
// baseline (speedup 1.0000x reference)
#include <cuda_runtime.h>

typedef unsigned long long u64;

#define CH_IN 32
#define CH_Y  16
#define WDIM  256
#define PLANE (256*256)
#define NTHR  128           // 2 rows/CTA: thread t -> row t/64, pixel quad (t%64)*4

__device__ __forceinline__ u64 pack2(float lo, float hi) {
    u64 r; asm("mov.b64 %0, {%1, %2};" : "=l"(r) : "f"(lo), "f"(hi)); return r;
}
__device__ __forceinline__ u64 dup2(float w) {
    u64 r; asm("mov.b64 %0, {%1, %1};" : "=l"(r) : "f"(w)); return r;
}
__device__ __forceinline__ void ffma2(u64& d, u64 a, u64 b) {
    asm("fma.rn.f32x2 %0, %1, %2, %0;" : "+l"(d) : "l"(a), "l"(b));
}
__device__ __forceinline__ u64 mul2(u64 a, u64 b) {
    u64 r; asm("mul.rn.f32x2 %0, %1, %2;" : "=l"(r) : "l"(a), "l"(b)); return r;
}
__device__ __forceinline__ float lo2(u64 v) {
    float lo, hi; asm("mov.b64 {%0, %1}, %2;" : "=f"(lo), "=f"(hi) : "l"(v)); return lo;
}
__device__ __forceinline__ float hi2(u64 v) {
    float lo, hi; asm("mov.b64 {%0, %1}, %2;" : "=f"(lo), "=f"(hi) : "l"(v)); return hi;
}

__global__ __launch_bounds__(NTHR, 3)
void cross_modal_attn_kernel(
    const float* __restrict__ c,  const float* __restrict__ p,
    const float* __restrict__ Wq, const float* __restrict__ bq,
    const float* __restrict__ Wk, const float* __restrict__ bk,
    const float* __restrict__ Wv, const float* __restrict__ bv,
    const float* __restrict__ Wy, const float* __restrict__ by,
    float* __restrict__ out)
{
    const int tid  = threadIdx.x;
    const int lane = tid & 31;
    const int rloc = tid >> 6;          // row within CTA (0,1)
    const int wrow = (tid >> 5) & 1;    // warp within row (0,1)
    const int qi   = tid & 63;          // pixel-quad index in row
    const int h    = blockIdx.x * 2 + rloc;
    const int b    = blockIdx.y;

    __shared__ float4 sWq[CH_Y*CH_IN/4], sWk[CH_Y*CH_IN/4], sWv[CH_Y*CH_IN/4];
    __shared__ float4 sWy[CH_IN*CH_Y/4];
    __shared__ float sbq[CH_Y], sbk[CH_Y], sbv[CH_Y], sby[CH_IN];
    __shared__ float sred[2][CH_Y][3];  // [row][channel][warp-in-row], padded
    __shared__ float sfin[2][CH_Y];

    {
        float* dWq = (float*)sWq; float* dWk = (float*)sWk;
        float* dWv = (float*)sWv; float* dWy = (float*)sWy;
        for (int i = tid; i < CH_Y*CH_IN; i += NTHR) {
            dWq[i] = Wq[i]; dWk[i] = Wk[i]; dWv[i] = Wv[i]; dWy[i] = Wy[i];
        }
    }
    if (tid < CH_Y)  { sbq[tid] = bq[tid]; sbk[tid] = bk[tid]; sbv[tid] = bv[tid]; }
    if (tid < CH_IN) { sby[tid] = by[tid]; }
    __syncthreads();

    const size_t base_in4  = (((size_t)b * CH_IN) * PLANE + (size_t)h * WDIM) / 4 + qi;
    const size_t base_out4 = (((size_t)b * (2*CH_IN)) * PLANE + (size_t)h * WDIM) / 4 + qi;
    const float4* p4 = (const float4*)p;
    const float4* c4 = (const float4*)c;
    float4* o4 = (float4*)out;
    const size_t cs4 = PLANE / 4;       // channel stride in float4

    // ---- Phase A: c -> q (quad packed as lo/hi u64 pairs) + concat copy ----
    u64 aql[CH_Y], aqh[CH_Y];
#pragma unroll
    for (int cy = 0; cy < CH_Y; cy++) { aql[cy] = dup2(sbq[cy]); aqh[cy] = dup2(sbq[cy]); }

#pragma unroll
    for (int ch = 0; ch < 4; ch++) {    // 4 chunks of 8 channels
        u64 xl[8], xh[8];
#pragma unroll
        for (int j = 0; j < 8; j++) {
            float4 v4 = __ldcs(c4 + base_in4 + (size_t)(ch*8 + j) * cs4);
            __stcs(o4 + base_out4 + (size_t)(CH_IN + ch*8 + j) * cs4, v4);
            xl[j] = pack2(v4.x, v4.y); xh[j] = pack2(v4.z, v4.w);
        }
#pragma unroll
        for (int cy = 0; cy < CH_Y; cy++) {
#pragma unroll
            for (int j4 = 0; j4 < 2; j4++) {
                const float4 wq = sWq[cy*(CH_IN/4) + ch*2 + j4];
                u64 w0 = dup2(wq.x), w1 = dup2(wq.y), w2 = dup2(wq.z), w3 = dup2(wq.w);
                ffma2(aql[cy], w0, xl[4*j4+0]); ffma2(aqh[cy], w0, xh[4*j4+0]);
                ffma2(aql[cy], w1, xl[4*j4+1]); ffma2(aqh[cy], w1, xh[4*j4+1]);
                ffma2(aql[cy], w2, xl[4*j4+2]); ffma2(aqh[cy], w2, xh[4*j4+2]);
                ffma2(aql[cy], w3, xl[4*j4+3]); ffma2(aqh[cy], w3, xh[4*j4+3]);
            }
        }
    }

    // ---- Phase B: p -> k (default caching: keep row hot in L2 for reload) ----
    u64 kkl[CH_Y], kkh[CH_Y];
#pragma unroll
    for (int cy = 0; cy < CH_Y; cy++) { kkl[cy] = dup2(sbk[cy]); kkh[cy] = dup2(sbk[cy]); }

#pragma unroll
    for (int ch = 0; ch < 4; ch++) {
        u64 xl[8], xh[8];
#pragma unroll
        for (int j = 0; j < 8; j++) {
            float4 v4 = __ldg(p4 + base_in4 + (size_t)(ch*8 + j) * cs4);
            xl[j] = pack2(v4.x, v4.y); xh[j] = pack2(v4.z, v4.w);
        }
#pragma unroll
        for (int cy = 0; cy < CH_Y; cy++) {
#pragma unroll
            for (int j4 = 0; j4 < 2; j4++) {
                const float4 wk = sWk[cy*(CH_IN/4) + ch*2 + j4];
                u64 w0 = dup2(wk.x), w1 = dup2(wk.y), w2 = dup2(wk.z), w3 = dup2(wk.w);
                ffma2(kkl[cy], w0, xl[4*j4+0]); ffma2(kkh[cy], w0, xh[4*j4+0]);
                ffma2(kkl[cy], w1, xl[4*j4+1]); ffma2(kkh[cy], w1, xh[4*j4+1]);
                ffma2(kkl[cy], w2, xl[4*j4+2]); ffma2(kkh[cy], w2, xh[4*j4+2]);
                ffma2(kkl[cy], w3, xl[4*j4+3]); ffma2(kkh[cy], w3, xh[4*j4+3]);
            }
        }
    }

    // ---- Phase C: t = exp(q*k) in place (no max-subtraction; |q*k| <~ 12) ----
#pragma unroll
    for (int cy = 0; cy < CH_Y; cy++) {
        u64 ql = mul2(aql[cy], kkl[cy]);
        u64 qh = mul2(aqh[cy], kkh[cy]);
        aql[cy] = pack2(__expf(lo2(ql)), __expf(hi2(ql)));
        aqh[cy] = pack2(__expf(lo2(qh)), __expf(hi2(qh)));
    }

    // ---- Phase D: row sum over 256 px = 4 px/thread + 64 threads (2 warps) ----
#pragma unroll
    for (int cy = 0; cy < CH_Y; cy++) {
        float s = lo2(aql[cy]) + hi2(aql[cy]) + lo2(aqh[cy]) + hi2(aqh[cy]);
#pragma unroll
        for (int o = 16; o; o >>= 1) s += __shfl_xor_sync(0xffffffffu, s, o);
        if (lane == 0) sred[rloc][cy][wrow] = s;
    }
    __syncthreads();
    if (tid < 2*CH_Y) {
        const int rr = tid >> 4, cy = tid & 15;
        sfin[rr][cy] = 1.0f / (sred[rr][cy][0] + sred[rr][cy][1]);
    }
    __syncthreads();

    // ---- Phase E: reload p (L2-hot), v on the fly, fold y = t*rinv*v ----
    u64 vvl[CH_Y], vvh[CH_Y];
#pragma unroll
    for (int cy = 0; cy < CH_Y; cy++) { vvl[cy] = dup2(sbv[cy]); vvh[cy] = dup2(sbv[cy]); }

#pragma unroll
    for (int ch = 0; ch < 4; ch++) {
        u64 xl[8], xh[8];
#pragma unroll
        for (int j = 0; j < 8; j++) {
            float4 v4 = __ldcs(p4 + base_in4 + (size_t)(ch*8 + j) * cs4);
            xl[j] = pack2(v4.x, v4.y); xh[j] = pack2(v4.z, v4.w);
        }
#pragma unroll
        for (int cy = 0; cy < CH_Y; cy++) {
#pragma unroll
            for (int j4 = 0; j4 < 2; j4++) {
                const float4 wv = sWv[cy*(CH_IN/4) + ch*2 + j4];
                u64 w0 = dup2(wv.x), w1 = dup2(wv.y), w2 = dup2(wv.z), w3 = dup2(wv.w);
                ffma2(vvl[cy], w0, xl[4*j4+0]); ffma2(vvh[cy], w0, xh[4*j4+0]);
                ffma2(vvl[cy], w1, xl[4*j4+1]); ffma2(vvh[cy], w1, xh[4*j4+1]);
                ffma2(vvl[cy], w2, xl[4*j4+2]); ffma2(vvh[cy], w2, xh[4*j4+2]);
                ffma2(vvl[cy], w3, xl[4*j4+3]); ffma2(vvh[cy], w3, xh[4*j4+3]);
            }
        }
    }

#pragma unroll
    for (int cy = 0; cy < CH_Y; cy++) {
        const u64 ri = dup2(sfin[rloc][cy]);
        aql[cy] = mul2(mul2(aql[cy], ri), vvl[cy]);
        aqh[cy] = mul2(mul2(aqh[cy], ri), vvh[cy]);
    }

    // ---- Phase F: output conv 16->32 on the pixel quad ----
#pragma unroll
    for (int co = 0; co < CH_IN; co++) {
        u64 al = dup2(sby[co]), ah = dup2(sby[co]);
#pragma unroll
        for (int j4 = 0; j4 < CH_Y/4; j4++) {
            const float4 wy = sWy[co*(CH_Y/4) + j4];
            u64 w0 = dup2(wy.x), w1 = dup2(wy.y), w2 = dup2(wy.z), w3 = dup2(wy.w);
            ffma2(al, w0, aql[4*j4+0]); ffma2(ah, w0, aqh[4*j4+0]);
            ffma2(al, w1, aql[4*j4+1]); ffma2(ah, w1, aqh[4*j4+1]);
            ffma2(al, w2, aql[4*j4+2]); ffma2(ah, w2, aqh[4*j4+2]);
            ffma2(al, w3, aql[4*j4+3]); ffma2(ah, w3, aqh[4*j4+3]);
        }
        float4 w4;
        w4.x = lo2(al); w4.y = hi2(al); w4.z = lo2(ah); w4.w = hi2(ah);
        __stcs(o4 + base_out4 + (size_t)co * cs4, w4);
    }
}

extern "C" void kernel_launch(void* const* d_in, const int* in_sizes, int n_in,
                              void* d_out, int out_size)
{
    const float* c  = (const float*)d_in[0];
    const float* p  = (const float*)d_in[1];
    const float* Wq = (const float*)d_in[2];
    const float* bq = (const float*)d_in[3];
    const float* Wk = (const float*)d_in[4];
    const float* bk = (const float*)d_in[5];
    const float* Wv = (const float*)d_in[6];
    const float* bv = (const float*)d_in[7];
    const float* Wy = (const float*)d_in[8];
    const float* by = (const float*)d_in[9];
    float* out = (float*)d_out;

    dim3 grid(WDIM / 2, 16);   // (128, 16) = 2048 CTAs, 2 rows each
    dim3 block(NTHR);          // 128 threads; 64 per row, 4 px per thread
    cross_modal_attn_kernel<<<grid, block>>>(c, p, Wq, bq, Wk, bk, Wv, bv, Wy, by, out);
}